// round 12
// baseline (speedup 1.0000x reference)
#include <cuda_runtime.h>
#include <cuda_fp16.h>
#include <cstdint>
#include <cstring>

// ============================================================================
// SumConv via mma.sync (HMMA f16, compute_103-safe), two kernels + PDL.
//   out[b,f,co] = log( sum_ci exp(ll[b,f,ci]) * softmax_ci(logits)[co,ci,kh,kw] )
// Single-term fp16 GEMM (rel_err ~1.5e-4 vs 1e-3 threshold).
// Kernel 1 (primary): softmax weights -> f16 pre-swizzled image g_wimg[g] (8KB);
//   signals griddepcontrol.launch_dependents at the end.
// Kernel 2 (secondary, PSS): 1024 CTAs = 16 groups x 64 tiles(16 rows), 128 thr
//   (4 warps, each m16n16). Small CTAs -> ~7 CTAs/SM -> barrier convoys
//   interleave across CTAs (issue-limited regime, see R11 post-mortem).
// ============================================================================

#define SWZ(x) ((x) ^ (((x) >> 3) & 0x70))

__device__ __forceinline__ uint32_t smem_u32(const void* p) {
    uint32_t a;
    asm("{ .reg .u64 t; cvta.to.shared.u64 t, %1; cvt.u32.u64 %0, t; }" : "=r"(a) : "l"(p));
    return a;
}

#define LDSM_X4(r0, r1, r2, r3, addr) \
    asm volatile("ldmatrix.sync.aligned.m8n8.x4.shared.b16 {%0,%1,%2,%3}, [%4];" \
        : "=r"(r0), "=r"(r1), "=r"(r2), "=r"(r3) : "r"(addr))

#define MMA_F16(D, A, B0, B1) \
    asm volatile("mma.sync.aligned.m16n8k16.row.col.f32.f16.f16.f32 " \
        "{%0,%1,%2,%3}, {%4,%5,%6,%7}, {%8,%9}, {%0,%1,%2,%3};" \
        : "+f"(D[0]), "+f"(D[1]), "+f"(D[2]), "+f"(D[3]) \
        : "r"(A[0]), "r"(A[1]), "r"(A[2]), "r"(A[3]), "r"(B0), "r"(B1))

// Pre-swizzled f16 weight image per group: 64 rows (co) x 128B (64 f16 ci).
__device__ __align__(16) unsigned char g_wimg[16][8192];

// ---------------------------------------------------------------------------
// Kernel 1: per-co softmax over ci for all 16 groups. Block = co (64 blocks).
// ---------------------------------------------------------------------------
__global__ __launch_bounds__(256) void weights_kernel(const float* __restrict__ logits)
{
    __shared__ float red[8][16];
    __shared__ float sinv[16];
    const int t = threadIdx.x, l = t & 31, w = t >> 5;
    const int co = blockIdx.x;
    const int ci = t >> 2;
    const int qb = (t & 3) << 2;

    float4 v = *(const float4*)(logits + co * 1024 + 4 * t);
    float e0 = __expf(v.x), e1 = __expf(v.y), e2 = __expf(v.z), e3 = __expf(v.w);

    float p0 = e0, p1 = e1, p2 = e2, p3 = e3;
    #pragma unroll
    for (int off = 4; off <= 16; off <<= 1) {
        p0 += __shfl_xor_sync(0xFFFFFFFFu, p0, off);
        p1 += __shfl_xor_sync(0xFFFFFFFFu, p1, off);
        p2 += __shfl_xor_sync(0xFFFFFFFFu, p2, off);
        p3 += __shfl_xor_sync(0xFFFFFFFFu, p3, off);
    }
    if (l < 4) {
        red[w][qb + 0] = p0; red[w][qb + 1] = p1;
        red[w][qb + 2] = p2; red[w][qb + 3] = p3;
    }
    __syncthreads();
    if (t < 16) {
        float s = 0.0f;
        #pragma unroll
        for (int ww = 0; ww < 8; ww++) s += red[ww][t];
        sinv[t] = __frcp_rn(s);
    }
    __syncthreads();

    const float wv[4] = { e0 * sinv[qb + 0], e1 * sinv[qb + 1],
                          e2 * sinv[qb + 2], e3 * sinv[qb + 3] };
    const bool even = ((ci & 1) == 0);     // lane l^4 holds ci^1, same group set
    #pragma unroll
    for (int j = 0; j < 4; j++) {
        __half hb = __float2half_rn(wv[j]);
        unsigned short hu; memcpy(&hu, &hb, 2);
        unsigned int hpart = __shfl_xor_sync(0xFFFFFFFFu, (unsigned int)hu, 4);
        if (even) {
            unsigned int hv = (unsigned int)hu | (hpart << 16);
            int g = qb + j;
            uint32_t off = SWZ((uint32_t)(co * 128 + ci * 2));   // 4B-aligned
            *(unsigned int*)(g_wimg[g] + off) = hv;
        }
    }
    asm volatile("griddepcontrol.launch_dependents;" ::: "memory");
}

// ---------------------------------------------------------------------------
// Kernel 2: main GEMM+log. SMEM: A(f16, 16x64) 2K | W(f16, 64x64) 8K = 10K.
// ---------------------------------------------------------------------------
static constexpr int S_A = 0;
static constexpr int S_B = 2048;

__global__ __launch_bounds__(128) void sumconv_mma_kernel(
    const float* __restrict__ ll, float* __restrict__ out)
{
    __shared__ __align__(1024) unsigned char sm[10240];
    const uint32_t sa = smem_u32(sm);

    const int t   = threadIdx.x;
    const int wid = t >> 5;
    const int lid = t & 31;

    const int g    = blockIdx.x >> 6;    // group = kh*4 + kw
    const int tile = blockIdx.x & 63;    // 16-row M tile
    const int kh = g >> 2, kw = g & 3;
    const int fbase = kh * 32 + kw;

    // ---- Prologue (independent of weights): E loads, exp, f16 pack, A store ----
    // Thread covers row r = t>>3 (0..15), ci chunk c8 = (t&7)*8 (16B smem chunk).
    {
        const int r  = t >> 3;
        const int c8 = (t & 7) << 3;
        int ridx = tile * 16 + r;
        int b    = ridx >> 6;
        int pos  = ridx & 63;
        int f    = ((pos >> 3) << 7) + ((pos & 7) << 2) + fbase;
        const float* src = ll + ((((b << 10) + f) << 6) + c8);
        float4 v0 = *(const float4*)(src);
        float4 v1 = *(const float4*)(src + 4);

        __half2 h0 = __floats2half2_rn(__expf(v0.x), __expf(v0.y));
        __half2 h1 = __floats2half2_rn(__expf(v0.z), __expf(v0.w));
        __half2 h2 = __floats2half2_rn(__expf(v1.x), __expf(v1.y));
        __half2 h3 = __floats2half2_rn(__expf(v1.z), __expf(v1.w));

        uint4 pk;
        memcpy(&pk.x, &h0, 4); memcpy(&pk.y, &h1, 4);
        memcpy(&pk.z, &h2, 4); memcpy(&pk.w, &h3, 4);
        *(uint4*)(sm + S_A + SWZ((uint32_t)(r * 128 + c8 * 2))) = pk;
    }

    // ---- Wait for weights kernel memory, then async-copy the 8KB W image ----
    asm volatile("griddepcontrol.wait;" ::: "memory");
    {
        const char* wg = (const char*)(g_wimg[g]) + 16 * t;
        #pragma unroll
        for (int i = 0; i < 4; i++) {
            asm volatile("cp.async.cg.shared.global [%0], [%1], 16;"
                         :: "r"(sa + S_B + 16 * t + 2048 * i),
                            "l"(wg + 2048 * i) : "memory");
        }
        asm volatile("cp.async.commit_group;" ::: "memory");
        asm volatile("cp.async.wait_group 0;" ::: "memory");
    }
    __syncthreads();

    // ---- MMA: warp -> m16 (all 16 rows) x n16 (cols 16*wid) ----
    const int nbase = 16 * wid;

    const uint32_t a_row = (lid & 7) + ((lid >> 3) & 1) * 8;
    const uint32_t a_kb  = ((lid >> 4) & 1) * 16;
    const uint32_t b_row = nbase + (lid & 7) + ((lid >> 4) & 1) * 8;
    const uint32_t b_kb  = ((lid >> 3) & 1) * 16;

    float acc[2][4];
    #pragma unroll
    for (int j = 0; j < 2; j++)
        #pragma unroll
        for (int q = 0; q < 4; q++) acc[j][q] = 0.0f;

    #pragma unroll
    for (int kc = 0; kc < 4; kc++) {
        uint32_t a[4], bt[4];
        LDSM_X4(a[0], a[1], a[2], a[3],     sa + S_A + SWZ(a_row * 128 + kc * 32 + a_kb));
        LDSM_X4(bt[0], bt[1], bt[2], bt[3], sa + S_B + SWZ(b_row * 128 + kc * 32 + b_kb));
        MMA_F16(acc[0], a, bt[0], bt[1]);
        MMA_F16(acc[1], a, bt[2], bt[3]);
    }

    // ---- Epilogue: log + store ----
    {
        int r0 = lid >> 2;
        int r1 = r0 + 8;
        int cb = nbase + 2 * (lid & 3);

        int ridx0 = tile * 16 + r0;
        int b0 = ridx0 >> 6, p0 = ridx0 & 63;
        int f0 = ((p0 >> 3) << 7) + ((p0 & 7) << 2) + fbase;
        float* ob0 = out + ((((b0 << 10) + f0) << 6) + cb);

        int ridx1 = tile * 16 + r1;
        int b1 = ridx1 >> 6, p1 = ridx1 & 63;
        int f1 = ((p1 >> 3) << 7) + ((p1 & 7) << 2) + fbase;
        float* ob1 = out + ((((b1 << 10) + f1) << 6) + cb);

        #pragma unroll
        for (int j = 0; j < 2; j++) {
            float2 o0, o1;
            o0.x = __logf(acc[j][0]);
            o0.y = __logf(acc[j][1]);
            o1.x = __logf(acc[j][2]);
            o1.y = __logf(acc[j][3]);
            *(float2*)(ob0 + 8 * j) = o0;
            *(float2*)(ob1 + 8 * j) = o1;
        }
    }
}

// ---------------------------------------------------------------------------
extern "C" void kernel_launch(void* const* d_in, const int* in_sizes, int n_in,
                              void* d_out, int out_size)
{
    const float* ll     = (const float*)d_in[0];   // (16,1024,64,1)
    const float* logits = (const float*)d_in[1];   // (64,64,4,4,1)
    float* out          = (float*)d_out;           // (16,1024,64,1)

    weights_kernel<<<64, 256>>>(logits);

    cudaLaunchConfig_t cfg = {};
    cfg.gridDim  = dim3(1024, 1, 1);
    cfg.blockDim = dim3(128, 1, 1);
    cfg.dynamicSmemBytes = 0;
    cfg.stream = (cudaStream_t)0;
    cudaLaunchAttribute attr;
    attr.id = cudaLaunchAttributeProgrammaticStreamSerialization;
    attr.val.programmaticStreamSerializationAllowed = 1;
    cfg.attrs = &attr;
    cfg.numAttrs = 1;
    cudaLaunchKernelEx(&cfg, sumconv_mma_kernel, ll, out);
}